// round 5
// baseline (speedup 1.0000x reference)
#include <cuda_runtime.h>

// MultitaskSNN: 5 LIF layers, T=50 steps, B=32768, fully batch-parallel.
// One thread per batch element; membranes in registers; weights in smem.
// Arithmetic matched to reference (XLA GPU):
//  - membrane update fma-contracted: m = fmaf(BETA, m, cur) - reset
//  - layer 1 (continuous input): gemm-style dot from 0, ascending k,
//    bias added as separate epilogue add (cuBLAS + bias fusion)
//  - binary layers: bias-seeded chains (bit-stable per R2 evidence)

namespace {
constexpr int T_STEPS = 50;
constexpr int B_SZ    = 32768;
constexpr float BETA  = 0.9f;
constexpr float TH    = 1.0f;

// output concat offsets (floats): (m_co[T,B,3], spk_ch[T,B,8], m_ro[T,B,1],
//                                  spk_rh[T,B,14], spk_sh[T,B,28])
constexpr size_t TB = (size_t)T_STEPS * B_SZ;
constexpr size_t O0 = 0;            // m_co
constexpr size_t O1 = TB * 3;       // spk_ch
constexpr size_t O2 = O1 + TB * 8;  // m_ro
constexpr size_t O3 = O2 + TB * 1;  // spk_rh
constexpr size_t O4 = O3 + TB * 14; // spk_sh

// smem layout (float offsets), all weight rows 16B-aligned
constexpr int SW_SH = 0;     // 28*32 = 896
constexpr int SB_SH = 896;   // 28
constexpr int SW_CH = 924;   // 8*28 = 224
constexpr int SB_CH = 1148;  // 8
constexpr int SW_CO = 1156;  // 3*8 = 24
constexpr int SB_CO = 1180;  // 3
constexpr int SW_RH = 1184;  // 14*28 = 392
constexpr int SB_RH = 1576;  // 14
constexpr int SW_RO = 1592;  // 14
constexpr int SB_RO = 1606;  // 1
constexpr int SMEM_F = 1608;
} // namespace

// Membrane update, fma-contracted (matches R2 bit-stable behavior):
// reset based on PREVIOUS membrane, then decay+integrate, then fire.
__device__ __forceinline__ float lif_update(float& m, float cur) {
    float r = (m > TH) ? TH : 0.0f;
    m = fmaf(BETA, m, cur) - r;
    return (m > TH) ? 1.0f : 0.0f;
}

__global__ void __launch_bounds__(128, 1)
snn_fused_kernel(const float* __restrict__ x,
                 const float* __restrict__ Wsh, const float* __restrict__ bsh,
                 const float* __restrict__ Wch, const float* __restrict__ bch,
                 const float* __restrict__ Wco, const float* __restrict__ bco,
                 const float* __restrict__ Wrh, const float* __restrict__ brh,
                 const float* __restrict__ Wro, const float* __restrict__ bro,
                 float* __restrict__ out)
{
    __shared__ __align__(16) float s[SMEM_F];
    const int tid = threadIdx.x;

    for (int i = tid; i < 896; i += 128) s[SW_SH + i] = Wsh[i];
    for (int i = tid; i < 224; i += 128) s[SW_CH + i] = Wch[i];
    for (int i = tid; i < 392; i += 128) s[SW_RH + i] = Wrh[i];
    if (tid < 28) s[SB_SH + tid] = bsh[tid];
    if (tid < 24) s[SW_CO + tid] = Wco[tid];
    if (tid < 14) s[SB_RH + tid] = brh[tid];
    if (tid < 14) s[SW_RO + tid] = Wro[tid];
    if (tid < 8)  s[SB_CH + tid] = bch[tid];
    if (tid < 3)  s[SB_CO + tid] = bco[tid];
    if (tid == 0) s[SB_RO] = bro[0];
    __syncthreads();

    const int b = blockIdx.x * 128 + tid;

    float m_sh[28], m_ch[8], m_co[3], m_rh[14], m_ro = 0.0f;
#pragma unroll
    for (int j = 0; j < 28; j++) m_sh[j] = 0.0f;
#pragma unroll
    for (int j = 0; j < 8;  j++) m_ch[j] = 0.0f;
#pragma unroll
    for (int j = 0; j < 3;  j++) m_co[j] = 0.0f;
#pragma unroll
    for (int j = 0; j < 14; j++) m_rh[j] = 0.0f;

    // prefetch x[t=0]
    float4 xbuf[8];
    {
        const float4* xp = reinterpret_cast<const float4*>(x) + (size_t)b * 8;
#pragma unroll
        for (int k = 0; k < 8; k++) xbuf[k] = __ldcs(xp + k);
    }

    for (int t = 0; t < T_STEPS; t++) {
        float4 xv[8];
#pragma unroll
        for (int k = 0; k < 8; k++) xv[k] = xbuf[k];
        if (t + 1 < T_STEPS) {
            const float4* xn = reinterpret_cast<const float4*>(x) +
                               ((size_t)(t + 1) * B_SZ + b) * 8;
#pragma unroll
            for (int k = 0; k < 8; k++) xbuf[k] = __ldcs(xn + k);
        }

        // ---- shared layer: gemm-style dot from 0, ascending k, then
        //      bias via separate rounded add (matches cuBLAS + epilogue) ----
        float acc[28];
#pragma unroll
        for (int j = 0; j < 28; j++) acc[j] = 0.0f;
#pragma unroll
        for (int kk = 0; kk < 8; kk++) {
            const float4 xq = xv[kk];
#pragma unroll
            for (int j = 0; j < 28; j++) {
                const float4 w = *reinterpret_cast<const float4*>(
                    &s[SW_SH + j * 32 + kk * 4]);
                acc[j] = fmaf(xq.x, w.x, acc[j]);
                acc[j] = fmaf(xq.y, w.y, acc[j]);
                acc[j] = fmaf(xq.z, w.z, acc[j]);
                acc[j] = fmaf(xq.w, w.w, acc[j]);
            }
        }

        float spk_sh[28];
#pragma unroll
        for (int j = 0; j < 28; j++)
            spk_sh[j] = lif_update(m_sh[j], __fadd_rn(acc[j], s[SB_SH + j]));

        const size_t row = (size_t)t * B_SZ + b;

        {   // store spk_sh (28 floats)
            float4* o = reinterpret_cast<float4*>(out + O4 + row * 28);
#pragma unroll
            for (int q = 0; q < 7; q++)
                __stcs(o + q, make_float4(spk_sh[4*q], spk_sh[4*q+1],
                                          spk_sh[4*q+2], spk_sh[4*q+3]));
        }

        // ---- class hidden: (8 x 28) on spk_sh, bias-seeded (R2 form) ----
        float spk_ch[8];
#pragma unroll
        for (int j = 0; j < 8; j++) {
            float a = s[SB_CH + j];
#pragma unroll
            for (int q = 0; q < 7; q++) {
                const float4 w = *reinterpret_cast<const float4*>(
                    &s[SW_CH + j * 28 + q * 4]);
                a = fmaf(spk_sh[4*q],   w.x, a);
                a = fmaf(spk_sh[4*q+1], w.y, a);
                a = fmaf(spk_sh[4*q+2], w.z, a);
                a = fmaf(spk_sh[4*q+3], w.w, a);
            }
            spk_ch[j] = lif_update(m_ch[j], a);
        }
        {
            float4* o = reinterpret_cast<float4*>(out + O1 + row * 8);
            __stcs(o,     make_float4(spk_ch[0], spk_ch[1], spk_ch[2], spk_ch[3]));
            __stcs(o + 1, make_float4(spk_ch[4], spk_ch[5], spk_ch[6], spk_ch[7]));
        }

        // ---- class out: (3 x 8) on spk_ch; only m_co recorded ----
#pragma unroll
        for (int j = 0; j < 3; j++) {
            float a = s[SB_CO + j];
#pragma unroll
            for (int q = 0; q < 2; q++) {
                const float4 w = *reinterpret_cast<const float4*>(
                    &s[SW_CO + j * 8 + q * 4]);
                a = fmaf(spk_ch[4*q],   w.x, a);
                a = fmaf(spk_ch[4*q+1], w.y, a);
                a = fmaf(spk_ch[4*q+2], w.z, a);
                a = fmaf(spk_ch[4*q+3], w.w, a);
            }
            (void)lif_update(m_co[j], a);
        }
        {
            float* o = out + O0 + row * 3;
            __stcs(o,     m_co[0]);
            __stcs(o + 1, m_co[1]);
            __stcs(o + 2, m_co[2]);
        }

        // ---- reg hidden: (14 x 28) on spk_sh, bias-seeded ----
        float spk_rh[14];
#pragma unroll
        for (int j = 0; j < 14; j++) {
            float a = s[SB_RH + j];
#pragma unroll
            for (int q = 0; q < 7; q++) {
                const float4 w = *reinterpret_cast<const float4*>(
                    &s[SW_RH + j * 28 + q * 4]);
                a = fmaf(spk_sh[4*q],   w.x, a);
                a = fmaf(spk_sh[4*q+1], w.y, a);
                a = fmaf(spk_sh[4*q+2], w.z, a);
                a = fmaf(spk_sh[4*q+3], w.w, a);
            }
            spk_rh[j] = lif_update(m_rh[j], a);
        }
        {
            float2* o = reinterpret_cast<float2*>(out + O3 + row * 14);
#pragma unroll
            for (int q = 0; q < 7; q++)
                __stcs(o + q, make_float2(spk_rh[2*q], spk_rh[2*q+1]));
        }

        // ---- reg out: (1 x 14) on spk_rh; only m_ro recorded ----
        {
            float a = s[SB_RO];
#pragma unroll
            for (int q = 0; q < 3; q++) {
                const float4 w = *reinterpret_cast<const float4*>(
                    &s[SW_RO + q * 4]);
                a = fmaf(spk_rh[4*q],   w.x, a);
                a = fmaf(spk_rh[4*q+1], w.y, a);
                a = fmaf(spk_rh[4*q+2], w.z, a);
                a = fmaf(spk_rh[4*q+3], w.w, a);
            }
            const float2 w2 = *reinterpret_cast<const float2*>(&s[SW_RO + 12]);
            a = fmaf(spk_rh[12], w2.x, a);
            a = fmaf(spk_rh[13], w2.y, a);
            (void)lif_update(m_ro, a);
            __stcs(out + O2 + row, m_ro);
        }
    }
}

extern "C" void kernel_launch(void* const* d_in, const int* in_sizes, int n_in,
                              void* d_out, int out_size)
{
    const float* x   = (const float*)d_in[0];
    const float* Wsh = (const float*)d_in[1];
    const float* bsh = (const float*)d_in[2];
    const float* Wch = (const float*)d_in[3];
    const float* bch = (const float*)d_in[4];
    const float* Wco = (const float*)d_in[5];
    const float* bco = (const float*)d_in[6];
    const float* Wrh = (const float*)d_in[7];
    const float* brh = (const float*)d_in[8];
    const float* Wro = (const float*)d_in[9];
    const float* bro = (const float*)d_in[10];
    float* out = (float*)d_out;

    snn_fused_kernel<<<B_SZ / 128, 128>>>(x, Wsh, bsh, Wch, bch, Wco, bco,
                                          Wrh, brh, Wro, bro, out);
}

// round 9
// speedup vs baseline: 1.0029x; 1.0029x over previous
#include <cuda_runtime.h>

// MultitaskSNN: 5 LIF layers, T=50 steps, B=32768, fully batch-parallel.
// One thread per batch element; membranes in registers; weights in smem.
// Arithmetic matched to reference (XLA GPU):
//  - membrane update fma-contracted: m = fmaf(BETA, m, cur) - reset
//  - layer 1 (continuous input): gemm-style dot from 0, ascending k,
//    bias added as separate epilogue add (cuBLAS + bias fusion)
//  - binary layers: bias-seeded chains (bit-stable per R2 evidence)

namespace {
constexpr int T_STEPS = 50;
constexpr int B_SZ    = 32768;
constexpr float BETA  = 0.9f;
constexpr float TH    = 1.0f;

// output concat offsets (floats): (m_co[T,B,3], spk_ch[T,B,8], m_ro[T,B,1],
//                                  spk_rh[T,B,14], spk_sh[T,B,28])
constexpr size_t TB = (size_t)T_STEPS * B_SZ;
constexpr size_t O0 = 0;            // m_co
constexpr size_t O1 = TB * 3;       // spk_ch
constexpr size_t O2 = O1 + TB * 8;  // m_ro
constexpr size_t O3 = O2 + TB * 1;  // spk_rh
constexpr size_t O4 = O3 + TB * 14; // spk_sh

// smem layout (float offsets), all weight rows 16B-aligned
constexpr int SW_SH = 0;     // 28*32 = 896
constexpr int SB_SH = 896;   // 28
constexpr int SW_CH = 924;   // 8*28 = 224
constexpr int SB_CH = 1148;  // 8
constexpr int SW_CO = 1156;  // 3*8 = 24
constexpr int SB_CO = 1180;  // 3
constexpr int SW_RH = 1184;  // 14*28 = 392
constexpr int SB_RH = 1576;  // 14
constexpr int SW_RO = 1592;  // 14
constexpr int SB_RO = 1606;  // 1
constexpr int SMEM_F = 1608;
} // namespace

// Membrane update, fma-contracted (matches R2 bit-stable behavior):
// reset based on PREVIOUS membrane, then decay+integrate, then fire.
__device__ __forceinline__ float lif_update(float& m, float cur) {
    float r = (m > TH) ? TH : 0.0f;
    m = fmaf(BETA, m, cur) - r;
    return (m > TH) ? 1.0f : 0.0f;
}

__global__ void __launch_bounds__(128, 1)
snn_fused_kernel(const float* __restrict__ x,
                 const float* __restrict__ Wsh, const float* __restrict__ bsh,
                 const float* __restrict__ Wch, const float* __restrict__ bch,
                 const float* __restrict__ Wco, const float* __restrict__ bco,
                 const float* __restrict__ Wrh, const float* __restrict__ brh,
                 const float* __restrict__ Wro, const float* __restrict__ bro,
                 float* __restrict__ out)
{
    __shared__ __align__(16) float s[SMEM_F];
    const int tid = threadIdx.x;

    for (int i = tid; i < 896; i += 128) s[SW_SH + i] = Wsh[i];
    for (int i = tid; i < 224; i += 128) s[SW_CH + i] = Wch[i];
    for (int i = tid; i < 392; i += 128) s[SW_RH + i] = Wrh[i];
    if (tid < 28) s[SB_SH + tid] = bsh[tid];
    if (tid < 24) s[SW_CO + tid] = Wco[tid];
    if (tid < 14) s[SB_RH + tid] = brh[tid];
    if (tid < 14) s[SW_RO + tid] = Wro[tid];
    if (tid < 8)  s[SB_CH + tid] = bch[tid];
    if (tid < 3)  s[SB_CO + tid] = bco[tid];
    if (tid == 0) s[SB_RO] = bro[0];
    __syncthreads();

    const int b = blockIdx.x * 128 + tid;

    float m_sh[28], m_ch[8], m_co[3], m_rh[14], m_ro = 0.0f;
#pragma unroll
    for (int j = 0; j < 28; j++) m_sh[j] = 0.0f;
#pragma unroll
    for (int j = 0; j < 8;  j++) m_ch[j] = 0.0f;
#pragma unroll
    for (int j = 0; j < 3;  j++) m_co[j] = 0.0f;
#pragma unroll
    for (int j = 0; j < 14; j++) m_rh[j] = 0.0f;

    // prefetch x[t=0]
    float4 xbuf[8];
    {
        const float4* xp = reinterpret_cast<const float4*>(x) + (size_t)b * 8;
#pragma unroll
        for (int k = 0; k < 8; k++) xbuf[k] = __ldcs(xp + k);
    }

    for (int t = 0; t < T_STEPS; t++) {
        float4 xv[8];
#pragma unroll
        for (int k = 0; k < 8; k++) xv[k] = xbuf[k];
        if (t + 1 < T_STEPS) {
            const float4* xn = reinterpret_cast<const float4*>(x) +
                               ((size_t)(t + 1) * B_SZ + b) * 8;
#pragma unroll
            for (int k = 0; k < 8; k++) xbuf[k] = __ldcs(xn + k);
        }

        // ---- shared layer: gemm-style dot from 0, ascending k, then
        //      bias via separate rounded add (matches cuBLAS + epilogue) ----
        float acc[28];
#pragma unroll
        for (int j = 0; j < 28; j++) acc[j] = 0.0f;
#pragma unroll
        for (int kk = 0; kk < 8; kk++) {
            const float4 xq = xv[kk];
#pragma unroll
            for (int j = 0; j < 28; j++) {
                const float4 w = *reinterpret_cast<const float4*>(
                    &s[SW_SH + j * 32 + kk * 4]);
                acc[j] = fmaf(xq.x, w.x, acc[j]);
                acc[j] = fmaf(xq.y, w.y, acc[j]);
                acc[j] = fmaf(xq.z, w.z, acc[j]);
                acc[j] = fmaf(xq.w, w.w, acc[j]);
            }
        }

        float spk_sh[28];
#pragma unroll
        for (int j = 0; j < 28; j++)
            spk_sh[j] = lif_update(m_sh[j], __fadd_rn(acc[j], s[SB_SH + j]));

        const size_t row = (size_t)t * B_SZ + b;

        {   // store spk_sh (28 floats)
            float4* o = reinterpret_cast<float4*>(out + O4 + row * 28);
#pragma unroll
            for (int q = 0; q < 7; q++)
                __stcs(o + q, make_float4(spk_sh[4*q], spk_sh[4*q+1],
                                          spk_sh[4*q+2], spk_sh[4*q+3]));
        }

        // ---- class hidden: (8 x 28) on spk_sh, bias-seeded (R2 form) ----
        float spk_ch[8];
#pragma unroll
        for (int j = 0; j < 8; j++) {
            float a = s[SB_CH + j];
#pragma unroll
            for (int q = 0; q < 7; q++) {
                const float4 w = *reinterpret_cast<const float4*>(
                    &s[SW_CH + j * 28 + q * 4]);
                a = fmaf(spk_sh[4*q],   w.x, a);
                a = fmaf(spk_sh[4*q+1], w.y, a);
                a = fmaf(spk_sh[4*q+2], w.z, a);
                a = fmaf(spk_sh[4*q+3], w.w, a);
            }
            spk_ch[j] = lif_update(m_ch[j], a);
        }
        {
            float4* o = reinterpret_cast<float4*>(out + O1 + row * 8);
            __stcs(o,     make_float4(spk_ch[0], spk_ch[1], spk_ch[2], spk_ch[3]));
            __stcs(o + 1, make_float4(spk_ch[4], spk_ch[5], spk_ch[6], spk_ch[7]));
        }

        // ---- class out: (3 x 8) on spk_ch; only m_co recorded ----
#pragma unroll
        for (int j = 0; j < 3; j++) {
            float a = s[SB_CO + j];
#pragma unroll
            for (int q = 0; q < 2; q++) {
                const float4 w = *reinterpret_cast<const float4*>(
                    &s[SW_CO + j * 8 + q * 4]);
                a = fmaf(spk_ch[4*q],   w.x, a);
                a = fmaf(spk_ch[4*q+1], w.y, a);
                a = fmaf(spk_ch[4*q+2], w.z, a);
                a = fmaf(spk_ch[4*q+3], w.w, a);
            }
            (void)lif_update(m_co[j], a);
        }
        {
            float* o = out + O0 + row * 3;
            __stcs(o,     m_co[0]);
            __stcs(o + 1, m_co[1]);
            __stcs(o + 2, m_co[2]);
        }

        // ---- reg hidden: (14 x 28) on spk_sh, bias-seeded ----
        float spk_rh[14];
#pragma unroll
        for (int j = 0; j < 14; j++) {
            float a = s[SB_RH + j];
#pragma unroll
            for (int q = 0; q < 7; q++) {
                const float4 w = *reinterpret_cast<const float4*>(
                    &s[SW_RH + j * 28 + q * 4]);
                a = fmaf(spk_sh[4*q],   w.x, a);
                a = fmaf(spk_sh[4*q+1], w.y, a);
                a = fmaf(spk_sh[4*q+2], w.z, a);
                a = fmaf(spk_sh[4*q+3], w.w, a);
            }
            spk_rh[j] = lif_update(m_rh[j], a);
        }
        {
            float2* o = reinterpret_cast<float2*>(out + O3 + row * 14);
#pragma unroll
            for (int q = 0; q < 7; q++)
                __stcs(o + q, make_float2(spk_rh[2*q], spk_rh[2*q+1]));
        }

        // ---- reg out: (1 x 14) on spk_rh; only m_ro recorded ----
        {
            float a = s[SB_RO];
#pragma unroll
            for (int q = 0; q < 3; q++) {
                const float4 w = *reinterpret_cast<const float4*>(
                    &s[SW_RO + q * 4]);
                a = fmaf(spk_rh[4*q],   w.x, a);
                a = fmaf(spk_rh[4*q+1], w.y, a);
                a = fmaf(spk_rh[4*q+2], w.z, a);
                a = fmaf(spk_rh[4*q+3], w.w, a);
            }
            const float2 w2 = *reinterpret_cast<const float2*>(&s[SW_RO + 12]);
            a = fmaf(spk_rh[12], w2.x, a);
            a = fmaf(spk_rh[13], w2.y, a);
            (void)lif_update(m_ro, a);
            __stcs(out + O2 + row, m_ro);
        }
    }
}

extern "C" void kernel_launch(void* const* d_in, const int* in_sizes, int n_in,
                              void* d_out, int out_size)
{
    const float* x   = (const float*)d_in[0];
    const float* Wsh = (const float*)d_in[1];
    const float* bsh = (const float*)d_in[2];
    const float* Wch = (const float*)d_in[3];
    const float* bch = (const float*)d_in[4];
    const float* Wco = (const float*)d_in[5];
    const float* bco = (const float*)d_in[6];
    const float* Wrh = (const float*)d_in[7];
    const float* brh = (const float*)d_in[8];
    const float* Wro = (const float*)d_in[9];
    const float* bro = (const float*)d_in[10];
    float* out = (float*)d_out;

    snn_fused_kernel<<<B_SZ / 128, 128>>>(x, Wsh, bsh, Wch, bch, Wco, bco,
                                          Wrh, brh, Wro, bro, out);
}